// round 11
// baseline (speedup 1.0000x reference)
#include <cuda_runtime.h>

#define N_NODES 40000
#define N_EDGES 640000
#define D 128
#define BM 64
#define CAP 64          // per-node bucket capacity (deg ~ Poisson(16))
#define XS_STRIDE 132

// Scratch (device globals — no allocation allowed)
__device__ float g_x[N_NODES * D];      // 20 MB: normalized x rows
__device__ float g_wt[D * D];           // W^T: g_wt[i*D + o] = W[o*D + i]
__device__ int   g_cur[N_NODES];        // bucket cursors == in-degree
__device__ int   g_bkt[N_NODES * CAP];  // 10 MB: src indices bucketed by dst

__device__ __forceinline__ bool idx_is64(const void* p) {
    const int* q = (const int*)p;
    return ((q[1] | q[3] | q[5] | q[7]) == 0);
}
__device__ __forceinline__ int load_idx(const void* p, int e, bool is64) {
    return is64 ? (int)reinterpret_cast<const long long*>(p)[e]
                : reinterpret_cast<const int*>(p)[e];
}

// ---------------------------------------------------------------------------
// 1) Bucket scatter (R6-proven: 1 edge/thread). Blocks >= 2500 transpose W.
// ---------------------------------------------------------------------------
__global__ void __launch_bounds__(256) scatter_kernel(
    const void* __restrict__ src, const void* __restrict__ dst,
    const float* __restrict__ W)
{
    int b = blockIdx.x, t = threadIdx.x;
    if (b >= N_EDGES / 256) {               // 64 W-transpose blocks
        int idx = (b - N_EDGES / 256) * 256 + t;
        g_wt[(idx & 127) * D + (idx >> 7)] = W[idx];
        return;
    }
    bool is64 = idx_is64(dst);
    int e = b * 256 + t;
    int d = load_idx(dst, e, is64);
    int s = load_idx(src, e, is64);
    int pos = atomicAdd(g_cur + d, 1);
    if (pos < CAP) g_bkt[d * CAP + pos] = s;
}

// ---------------------------------------------------------------------------
// 2) Aggregate (R6-proven): one warp per node, register gather-sum,
//    x = feat[d]*sum/max(deg,1).
// ---------------------------------------------------------------------------
__global__ void __launch_bounds__(256) agg_kernel(const float* __restrict__ feat)
{
    int n    = (blockIdx.x * 256 + threadIdx.x) >> 5;   // 5000 blocks * 8 warps
    int lane = threadIdx.x & 31;
    if (n >= N_NODES) return;

    int deg = min(g_cur[n], CAP);
    const int* bkt = g_bkt + n * CAP;

    float4 sum = make_float4(0.f, 0.f, 0.f, 0.f);
    for (int j = 0; j < deg; j += 32) {
        int m = min(32, deg - j);
        int myidx = (lane < m) ? bkt[j + lane] : 0;
        #pragma unroll 4
        for (int q = 0; q < m; ++q) {
            int s = __shfl_sync(0xffffffffu, myidx, q);
            float4 a = reinterpret_cast<const float4*>(feat + (size_t)s * D)[lane];
            sum.x += a.x; sum.y += a.y; sum.z += a.z; sum.w += a.w;
        }
    }

    float inv = 1.0f / (float)max(deg, 1);
    float4 f = reinterpret_cast<const float4*>(feat + (size_t)n * D)[lane];
    float4 x = make_float4(sum.x * f.x * inv, sum.y * f.y * inv,
                           sum.z * f.z * inv, sum.w * f.w * inv);
    reinterpret_cast<float4*>(g_x + (size_t)n * D)[lane] = x;
}

// ---------------------------------------------------------------------------
// 3) GEMM with k-pair-packed f32x2: acc lanes hold (even-k, odd-k) partial
//    sums. x pairs {x[2k],x[2k+1]} come straight from row-major xs via
//    ld.shared.u64 (no packing movs); W pre-interleaved in smem as
//    ws2[k2][c] = {W^T[2k2][c], W^T[2k2+1][c]} (col c at float offset c*2).
//    Per k2-step: 4 LDS.64 + 4 LDS.128 + 32 fma.f32x2 (80% FMA density).
// ---------------------------------------------------------------------------
__global__ void __launch_bounds__(256) gemm_kernel(
    const float* __restrict__ bias, float* __restrict__ out)
{
    extern __shared__ float smem[];
    float* ws2 = smem;                      // [64][128][2] = 16384 floats (64KB)
    float* xs  = smem + 2 * D * D;          // [64][132]

    const int t  = threadIdx.x;
    const int r0 = blockIdx.x * BM;         // 625 * 64 = 40000 exact
    const int tr = t >> 4;                  // rows tr*4..+3
    const int tc = t & 15;                  // cols tc*4..+3, 64+tc*4..+3

    // Stage W interleaved: thread handles (k2 = idx>>5, c4 = idx&31),
    // rows 2k2 / 2k2+1 of W^T, cols c4*4..+3. 2 LDG.128 + 2 STS.128.
    #pragma unroll
    for (int i = 0; i < 8; ++i) {
        int idx = i * 256 + t;              // 0..2047
        int k2 = idx >> 5;
        int c4 = idx & 31;
        float4 a = *(const float4*)(g_wt + (size_t)(2 * k2)     * D + c4 * 4);
        float4 b = *(const float4*)(g_wt + (size_t)(2 * k2 + 1) * D + c4 * 4);
        float* dp = ws2 + k2 * 256 + c4 * 8;
        *(float4*)(dp + 0) = make_float4(a.x, b.x, a.y, b.y);
        *(float4*)(dp + 4) = make_float4(a.z, b.z, a.w, b.w);
    }
    // Stage x tile (row-major, stride 132): thread owns row t>>2, quarter t&3.
    {
        const int xr = t >> 2;
        const int xq = t & 3;
        const float4* src4 = (const float4*)(g_x + (size_t)(r0 + xr) * D + xq * 32);
        float* dstp = xs + xr * XS_STRIDE + xq * 32;
        #pragma unroll
        for (int i = 0; i < 8; ++i)
            *(float4*)(dstp + i * 4) = src4[i];
    }
    __syncthreads();

    unsigned long long acc[4][8];           // [row j][col c8] = {even,odd} sums
    #pragma unroll
    for (int j = 0; j < 4; ++j)
        #pragma unroll
        for (int p = 0; p < 8; ++p) acc[j][p] = 0ULL;

    #pragma unroll 8
    for (int k2 = 0; k2 < D / 2; ++k2) {
        // x pairs: 4 rows, contiguous {x[2k2], x[2k2+1]} each.
        unsigned long long xp[4];
        #pragma unroll
        for (int j = 0; j < 4; ++j)
            xp[j] = *(const unsigned long long*)&xs[(tr * 4 + j) * XS_STRIDE + 2 * k2];

        // w pairs: cols tc*4..+3 at float offset tc*8; cols 64+tc*4..+3 at
        // float offset 128 + tc*8 (col c lives at c*2 within the 256-float row).
        ulonglong2 wA0 = *(const ulonglong2*)&ws2[k2 * 256 + tc * 8];
        ulonglong2 wA1 = *(const ulonglong2*)&ws2[k2 * 256 + tc * 8 + 4];
        ulonglong2 wB0 = *(const ulonglong2*)&ws2[k2 * 256 + 128 + tc * 8];
        ulonglong2 wB1 = *(const ulonglong2*)&ws2[k2 * 256 + 128 + tc * 8 + 4];

        #pragma unroll
        for (int j = 0; j < 4; ++j) {
            asm("fma.rn.f32x2 %0, %1, %2, %0;" : "+l"(acc[j][0]) : "l"(xp[j]), "l"(wA0.x));
            asm("fma.rn.f32x2 %0, %1, %2, %0;" : "+l"(acc[j][1]) : "l"(xp[j]), "l"(wA0.y));
            asm("fma.rn.f32x2 %0, %1, %2, %0;" : "+l"(acc[j][2]) : "l"(xp[j]), "l"(wA1.x));
            asm("fma.rn.f32x2 %0, %1, %2, %0;" : "+l"(acc[j][3]) : "l"(xp[j]), "l"(wA1.y));
            asm("fma.rn.f32x2 %0, %1, %2, %0;" : "+l"(acc[j][4]) : "l"(xp[j]), "l"(wB0.x));
            asm("fma.rn.f32x2 %0, %1, %2, %0;" : "+l"(acc[j][5]) : "l"(xp[j]), "l"(wB0.y));
            asm("fma.rn.f32x2 %0, %1, %2, %0;" : "+l"(acc[j][6]) : "l"(xp[j]), "l"(wB1.x));
            asm("fma.rn.f32x2 %0, %1, %2, %0;" : "+l"(acc[j][7]) : "l"(xp[j]), "l"(wB1.y));
        }
    }

    // Epilogue: v = even + odd (+ bias), store.
    float4 bA = *(const float4*)(bias + tc * 4);
    float4 bB = *(const float4*)(bias + 64 + tc * 4);
    #pragma unroll
    for (int j = 0; j < 4; ++j) {
        int r = r0 + tr * 4 + j;
        float e, o, v[8];
        #pragma unroll
        for (int p = 0; p < 8; ++p) {
            asm("mov.b64 {%0, %1}, %2;" : "=f"(e), "=f"(o) : "l"(acc[j][p]));
            v[p] = e + o;
        }
        float4 oA = make_float4(v[0] + bA.x, v[1] + bA.y, v[2] + bA.z, v[3] + bA.w);
        float4 oB = make_float4(v[4] + bB.x, v[5] + bB.y, v[6] + bB.z, v[7] + bB.w);
        *(float4*)(out + (size_t)r * D + tc * 4)      = oA;
        *(float4*)(out + (size_t)r * D + 64 + tc * 4) = oB;
    }
}

// ---------------------------------------------------------------------------
extern "C" void kernel_launch(void* const* d_in, const int* in_sizes, int n_in,
                              void* d_out, int out_size) {
    const float* feat = (const float*)d_in[0];
    const void*  src  = d_in[1];
    const void*  dst  = d_in[2];
    const float* W    = (const float*)d_in[3];
    const float* b    = (const float*)d_in[4];
    float*       out  = (float*)d_out;

    void* cur_ptr = nullptr;
    cudaGetSymbolAddress(&cur_ptr, g_cur);

    const int smem_bytes = (2 * D * D + BM * XS_STRIDE) * sizeof(float);  // 99328
    cudaFuncSetAttribute(gemm_kernel,
                         cudaFuncAttributeMaxDynamicSharedMemorySize, smem_bytes);

    cudaMemsetAsync(cur_ptr, 0, sizeof(int) * N_NODES);

    scatter_kernel<<<N_EDGES / 256 + 64, 256>>>(src, dst, W);  // + W^T blocks
    agg_kernel<<<(N_NODES * 32 + 255) / 256, 256>>>(feat);
    gemm_kernel<<<N_NODES / BM, 256, smem_bytes>>>(b, out);
}